// round 8
// baseline (speedup 1.0000x reference)
#include <cuda_runtime.h>
#include <cuda_fp16.h>
#include <cstdint>

// VQ quantizer: fp16 3-term-split HMMA + split accumulators + packed-key top-3.
// EXACT-PATH FIX vs R6/R7: rescue distances use plain ||c||^2 (R5 bit-exact
// semantics, proven rel_err=0.0). The +256 offset exists ONLY inside the
// screen key (positivity for uint ordering); it changed exact-path rounding
// on a near-tied token in R6/R7 and flipped its argmin vs the reference.
//
// dist_k = ||c_k||^2 - 2*<z,c_k>;  <z,c> = z_hi*c_hi + z_lo*c_hi + z_hi*c_lo
// (fp32 accum, err <= ~3e-4). Screen key: dist''=(||c||^2+256)-2*dot in
// (128,512) -> bits orderable; key=(bits&~511)|k, truncation <= 0.0156.
// DELTA=0.03 trigger: top-2 gap < DELTA -> exact fp32 rescore; top-3 gap
// < DELTA -> full exact scan. Exact path: fp32, strict <, first-index ties.

#define DQ        64
#define KC        512
#define ROWB      272                     // packed row: hi 128B | lo 128B | pad 16B
#define PACK_BYTES (KC * ROWB)            // 139264
#define THREADS   512
#define MROWS     256                     // 16 warps x 16 rows
#define DELTA     0.03f
#define OFFS      256.0f
#define SMEM_TOTAL (PACK_BYTES + KC * 4)

__device__ __align__(16) unsigned char g_cbpack[PACK_BYTES];
__device__ float g_cnorm[KC];             // plain ||c||^2 (NO offset)

// ---------------- helpers ----------------

__device__ __forceinline__ uint32_t smem_u32(const void* p) {
    uint32_t a;
    asm("{ .reg .u64 t; cvta.to.shared.u64 t, %1; cvt.u32.u64 %0, t; }" : "=r"(a) : "l"(p));
    return a;
}

__device__ __forceinline__ uint32_t pack2(__half a, __half b) {
    __half2 h = __halves2half2(a, b);
    return *reinterpret_cast<uint32_t*>(&h);
}

#define LDSM4(r0, r1, r2, r3, addr)                                         \
    asm volatile("ldmatrix.sync.aligned.m8n8.x4.shared.b16 {%0,%1,%2,%3}, [%4];" \
        : "=r"(r0), "=r"(r1), "=r"(r2), "=r"(r3) : "r"(addr))

#define MMA16816(c0, c1, c2, c3, a0, a1, a2, a3, b0, b1)                    \
    asm volatile("mma.sync.aligned.m16n8k16.row.col.f32.f16.f16.f32 "       \
        "{%0,%1,%2,%3}, {%4,%5,%6,%7}, {%8,%9}, {%0,%1,%2,%3};"             \
        : "+f"(c0), "+f"(c1), "+f"(c2), "+f"(c3)                            \
        : "r"(a0), "r"(a1), "r"(a2), "r"(a3), "r"(b0), "r"(b1))

// Sorted top-3 insert (a<=b<=c), 5 IMNMX.
__device__ __forceinline__ void ins3(uint32_t& a, uint32_t& b, uint32_t& c,
                                     uint32_t x) {
    uint32_t h1 = max(a, x); a = min(a, x);
    uint32_t h2 = max(b, h1); b = min(b, h1);
    c = min(c, h2);
}

// Screen key only: offset distance for positivity. NEVER used in exact path.
__device__ __forceinline__ uint32_t mkkey(float dot, float nrm, int k) {
    const float d = fmaf(-2.0f, dot, nrm + OFFS);
    return (__float_as_uint(d) & ~511u) | (uint32_t)k;
}

// R5 bit-exact offsetless distance (fp32, fixed fmaf accumulation order).
__device__ __forceinline__ float exact_dist(const float4* zv, const float* crow_f,
                                            float nrm) {
    const float4* crow = reinterpret_cast<const float4*>(crow_f);
    float s0 = 0.f, s1 = 0.f, s2 = 0.f, s3 = 0.f;
    #pragma unroll
    for (int i = 0; i < 16; i++) {
        float4 c = crow[i]; float4 z = zv[i];
        s0 = fmaf(z.x, c.x, s0); s1 = fmaf(z.y, c.y, s1);
        s2 = fmaf(z.z, c.z, s2); s3 = fmaf(z.w, c.w, s3);
    }
    return fmaf(-2.0f, (s0 + s1) + (s2 + s3), nrm);
}

// ---------------- prep: split codebook to fp16 hi|lo + norms ----------------

__global__ void prep_kernel(const float* __restrict__ cb) {
    const int k = threadIdx.x;
    if (k >= KC) return;
    const float4* row = reinterpret_cast<const float4*>(cb + (size_t)k * DQ);
    uint32_t* dst = reinterpret_cast<uint32_t*>(g_cbpack + (size_t)k * ROWB);
    float s0 = 0.f, s1 = 0.f, s2 = 0.f, s3 = 0.f;
    #pragma unroll
    for (int i = 0; i < 16; i++) {
        float4 f = row[i];
        s0 = fmaf(f.x, f.x, s0); s1 = fmaf(f.y, f.y, s1);
        s2 = fmaf(f.z, f.z, s2); s3 = fmaf(f.w, f.w, s3);
        __half hx = __float2half_rn(f.x), hy = __float2half_rn(f.y);
        __half hz = __float2half_rn(f.z), hw = __float2half_rn(f.w);
        dst[2*i]       = pack2(hx, hy);
        dst[2*i + 1]   = pack2(hz, hw);
        dst[32 + 2*i]     = pack2(__float2half_rn(f.x - __half2float(hx)),
                                  __float2half_rn(f.y - __half2float(hy)));
        dst[32 + 2*i + 1] = pack2(__float2half_rn(f.z - __half2float(hz)),
                                  __float2half_rn(f.w - __half2float(hw)));
    }
    g_cnorm[k] = (s0 + s1) + (s2 + s3);   // plain, no offset (R5 semantics)
}

// ---------------- main ----------------

__global__ __launch_bounds__(THREADS, 1)
void vq_main(const float* __restrict__ ze,
             const float* __restrict__ cb,
             float* __restrict__ out) {
    extern __shared__ char smem[];
    float* snrm = reinterpret_cast<float*>(smem + PACK_BYTES);

    // Cooperative copy: packed codebook + norms -> SMEM.
    {
        const uint4* src = reinterpret_cast<const uint4*>(g_cbpack);
        uint4* dst = reinterpret_cast<uint4*>(smem);
        for (int i = threadIdx.x; i < PACK_BYTES / 16; i += THREADS) dst[i] = src[i];
        for (int i = threadIdx.x; i < KC; i += THREADS) snrm[i] = g_cnorm[i];
    }

    const int tid  = threadIdx.x;
    const int w    = tid >> 5;
    const int lane = tid & 31;
    const int g    = lane >> 2;
    const int t    = lane & 3;
    const int row_base = blockIdx.x * MROWS + w * 16;

    // A fragments: Ah/Al[kt][2*h + rr]
    uint32_t Ah[4][4], Al[4][4];
    #pragma unroll
    for (int kt = 0; kt < 4; kt++)
        #pragma unroll
        for (int h = 0; h < 2; h++)
            #pragma unroll
            for (int rr = 0; rr < 2; rr++) {
                const int row = row_base + g + 8 * rr;
                const int col = kt * 16 + h * 8 + 2 * t;
                float2 f = *reinterpret_cast<const float2*>(ze + (size_t)row * DQ + col);
                __half hx = __float2half_rn(f.x), hy = __float2half_rn(f.y);
                Ah[kt][2*h + rr] = pack2(hx, hy);
                Al[kt][2*h + rr] = pack2(__float2half_rn(f.x - __half2float(hx)),
                                         __float2half_rn(f.y - __half2float(hy)));
            }
    __syncthreads();

    // Sorted top-3 keys per row slot (slot0: row g, slot1: row g+8).
    uint32_t K1[2], K2[2], K3[2];
    #pragma unroll
    for (int s = 0; s < 2; s++) { K1[s] = K2[s] = K3[s] = 0xFFFFFFFFu; }

    const uint32_t smem_u = smem_u32(smem);
    const int      brow = ((lane >> 4) & 1) * 8 + (lane & 7);
    const uint32_t koff = ((lane >> 3) & 1) * 16;

    #pragma unroll 1
    for (int c = 0; c < KC / 16; c++) {
        const int n0 = c * 16;
        const uint32_t bbase = smem_u + (uint32_t)(n0 + brow) * ROWB + koff;

        // 3 segment accumulators x 2 n-tiles: 6 independent depth-4 chains.
        float aH[2][4], aL[2][4], aX[2][4];
        #pragma unroll
        for (int nt = 0; nt < 2; nt++)
            #pragma unroll
            for (int q = 0; q < 4; q++) { aH[nt][q] = 0.f; aL[nt][q] = 0.f; aX[nt][q] = 0.f; }

        uint32_t Bh[4][4], Bl[4][4];
        #pragma unroll
        for (int kt = 0; kt < 4; kt++)
            LDSM4(Bh[kt][0], Bh[kt][1], Bh[kt][2], Bh[kt][3], bbase + kt * 32);
        #pragma unroll
        for (int kt = 0; kt < 4; kt++)
            LDSM4(Bl[kt][0], Bl[kt][1], Bl[kt][2], Bl[kt][3], bbase + 128 + kt * 32);

        #pragma unroll
        for (int kt = 0; kt < 4; kt++) {
            MMA16816(aH[0][0], aH[0][1], aH[0][2], aH[0][3],
                     Ah[kt][0], Ah[kt][1], Ah[kt][2], Ah[kt][3], Bh[kt][0], Bh[kt][1]);
            MMA16816(aH[1][0], aH[1][1], aH[1][2], aH[1][3],
                     Ah[kt][0], Ah[kt][1], Ah[kt][2], Ah[kt][3], Bh[kt][2], Bh[kt][3]);
            MMA16816(aL[0][0], aL[0][1], aL[0][2], aL[0][3],
                     Al[kt][0], Al[kt][1], Al[kt][2], Al[kt][3], Bh[kt][0], Bh[kt][1]);
            MMA16816(aL[1][0], aL[1][1], aL[1][2], aL[1][3],
                     Al[kt][0], Al[kt][1], Al[kt][2], Al[kt][3], Bh[kt][2], Bh[kt][3]);
            MMA16816(aX[0][0], aX[0][1], aX[0][2], aX[0][3],
                     Ah[kt][0], Ah[kt][1], Ah[kt][2], Ah[kt][3], Bl[kt][0], Bl[kt][1]);
            MMA16816(aX[1][0], aX[1][1], aX[1][2], aX[1][3],
                     Ah[kt][0], Ah[kt][1], Ah[kt][2], Ah[kt][3], Bl[kt][2], Bl[kt][3]);
        }

        // Epilogue: dot = aH + aL + aX; offset key; top-3.
        const float2 cn0 = *reinterpret_cast<const float2*>(&snrm[n0 + 2 * t]);
        const float2 cn1 = *reinterpret_cast<const float2*>(&snrm[n0 + 8 + 2 * t]);
        #pragma unroll
        for (int nt = 0; nt < 2; nt++) {
            const float cA = nt ? cn1.x : cn0.x;
            const float cB = nt ? cn1.y : cn0.y;
            const int colA = n0 + nt * 8 + 2 * t;
            const float d0 = (aH[nt][0] + aL[nt][0]) + aX[nt][0];
            const float d1 = (aH[nt][1] + aL[nt][1]) + aX[nt][1];
            const float d2 = (aH[nt][2] + aL[nt][2]) + aX[nt][2];
            const float d3 = (aH[nt][3] + aL[nt][3]) + aX[nt][3];
            ins3(K1[0], K2[0], K3[0], mkkey(d0, cA, colA));
            ins3(K1[0], K2[0], K3[0], mkkey(d1, cB, colA + 1));
            ins3(K1[1], K2[1], K3[1], mkkey(d2, cA, colA));
            ins3(K1[1], K2[1], K3[1], mkkey(d3, cB, colA + 1));
        }
    }

    // Cross-lane merge (lanes 4g..4g+3 share rows g, g+8).
    #pragma unroll
    for (int xo = 1; xo <= 2; xo <<= 1) {
        #pragma unroll
        for (int s = 0; s < 2; s++) {
            uint32_t o1 = __shfl_xor_sync(0xFFFFFFFFu, K1[s], xo);
            uint32_t o2 = __shfl_xor_sync(0xFFFFFFFFu, K2[s], xo);
            uint32_t o3 = __shfl_xor_sync(0xFFFFFFFFu, K3[s], xo);
            ins3(K1[s], K2[s], K3[s], o1);
            ins3(K1[s], K2[s], K3[s], o2);
            ins3(K1[s], K2[s], K3[s], o3);
        }
    }

    // Resolution: lane 4g+t owns row g+8t for t<2. Exact path = R5 semantics.
    int kw = 0;
    if (t < 2) {
        const int my_row = row_base + g + 8 * t;
        const uint32_t key1 = K1[t], key2 = K2[t], key3 = K3[t];
        const int rk1 = (int)(key1 & 511u), rk2 = (int)(key2 & 511u);
        const float a1 = __uint_as_float(key1 & ~511u);
        const float a2 = __uint_as_float(key2 & ~511u);
        const float a3 = __uint_as_float(key3 & ~511u);
        kw = rk1;
        if (a3 - a1 < DELTA) {
            // Full exact fp32 scan (rare): plain norms, strict <, first index.
            float4 zv[16];
            const float4* zp = reinterpret_cast<const float4*>(ze + (size_t)my_row * DQ);
            #pragma unroll
            for (int i = 0; i < 16; i++) zv[i] = zp[i];
            float best = 3.4e38f; int bk = 0;
            for (int k = 0; k < KC; k++) {
                const float d = exact_dist(zv, cb + (size_t)k * DQ, snrm[k]);
                if (d < best) { best = d; bk = k; }
            }
            kw = bk;
        } else if (a2 - a1 < DELTA) {
            float4 zv[16];
            const float4* zp = reinterpret_cast<const float4*>(ze + (size_t)my_row * DQ);
            #pragma unroll
            for (int i = 0; i < 16; i++) zv[i] = zp[i];
            const float e1 = exact_dist(zv, cb + (size_t)rk1 * DQ, snrm[rk1]);
            const float e2 = exact_dist(zv, cb + (size_t)rk2 * DQ, snrm[rk2]);
            if (e2 < e1 || (e2 == e1 && rk2 < rk1)) kw = rk2;
        }
    }

    // Coalesced gather (codebook is L2-resident) + write.
    #pragma unroll 1
    for (int r = 0; r < 16; r++) {
        const int src_lane = 4 * (r & 7) + (r >> 3);
        const int kk = __shfl_sync(0xFFFFFFFFu, kw, src_lane);
        const float2 v = reinterpret_cast<const float2*>(cb + (size_t)kk * DQ)[lane];
        reinterpret_cast<float2*>(out + (size_t)(row_base + r) * DQ)[lane] = v;
    }
}

extern "C" void kernel_launch(void* const* d_in, const int* in_sizes, int n_in,
                              void* d_out, int out_size) {
    const float* ze = (const float*)d_in[0];
    const float* cb = (const float*)d_in[1];
    float* out = (float*)d_out;
    const int n_tokens = in_sizes[0] / DQ;
    const int grid = n_tokens / MROWS;   // 2048

    prep_kernel<<<1, KC>>>(cb);
    cudaFuncSetAttribute(vq_main,
                         cudaFuncAttributeMaxDynamicSharedMemorySize, SMEM_TOTAL);
    vq_main<<<grid, THREADS, SMEM_TOTAL>>>(ze, cb, out);
}